// round 13
// baseline (speedup 1.0000x reference)
#include <cuda_runtime.h>
#include <cuda_bf16.h>
#include <cstdint>

// Problem constants
#define B_  2
#define S_  2048
#define D_  1024
#define H_  16
#define DK_ 64
#define M_  (B_ * S_)   // 4096

// ---------------------------------------------------------------------------
// Scratch
// ---------------------------------------------------------------------------
__device__ __nv_bfloat16 g_Qh[M_ * D_];
__device__ __nv_bfloat16 g_Ql[M_ * D_];
__device__ __nv_bfloat16 g_Kh[M_ * D_];
__device__ __nv_bfloat16 g_Kl[M_ * D_];
__device__ __nv_bfloat16 g_Vh[M_ * D_];
__device__ __nv_bfloat16 g_Vl[M_ * D_];
__device__ __nv_bfloat16 g_Ch[M_ * D_];
__device__ __nv_bfloat16 g_Cl[M_ * D_];
__device__ __nv_bfloat16 g_Bias[(size_t)B_ * S_ * S_];   // mask -> additive bias

__device__ __forceinline__ uint32_t smem_u32(const void* p) {
    uint32_t a;
    asm("{ .reg .u64 t; cvta.to.shared.u64 t, %1; cvt.u32.u64 %0, t; }"
        : "=r"(a) : "l"(p));
    return a;
}

__device__ __forceinline__ void mma16816(float* c,
                                         uint32_t a0, uint32_t a1, uint32_t a2, uint32_t a3,
                                         uint32_t b0, uint32_t b1) {
    asm volatile(
        "mma.sync.aligned.m16n8k16.row.col.f32.bf16.bf16.f32 "
        "{%0,%1,%2,%3}, {%4,%5,%6,%7}, {%8,%9}, {%0,%1,%2,%3};"
        : "+f"(c[0]), "+f"(c[1]), "+f"(c[2]), "+f"(c[3])
        : "r"(a0), "r"(a1), "r"(a2), "r"(a3), "r"(b0), "r"(b1));
}

__device__ __forceinline__ void ldsm4(uint32_t* r, uint32_t addr) {
    asm volatile("ldmatrix.sync.aligned.m8n8.x4.shared.b16 {%0,%1,%2,%3}, [%4];"
                 : "=r"(r[0]), "=r"(r[1]), "=r"(r[2]), "=r"(r[3]) : "r"(addr));
}

__device__ __forceinline__ void ldsm4t(uint32_t* r, uint32_t addr) {
    asm volatile("ldmatrix.sync.aligned.m8n8.x4.trans.shared.b16 {%0,%1,%2,%3}, [%4];"
                 : "=r"(r[0]), "=r"(r[1]), "=r"(r[2]), "=r"(r[3]) : "r"(addr));
}

union PackB4 { uint64_t u; __nv_bfloat16 b[4]; };

__device__ __forceinline__ void split4(float4 v, uint64_t& hi, uint64_t& lo) {
    PackB4 h, l;
    h.b[0] = __float2bfloat16_rn(v.x);
    h.b[1] = __float2bfloat16_rn(v.y);
    h.b[2] = __float2bfloat16_rn(v.z);
    h.b[3] = __float2bfloat16_rn(v.w);
    l.b[0] = __float2bfloat16_rn(v.x - __bfloat162float(h.b[0]));
    l.b[1] = __float2bfloat16_rn(v.y - __bfloat162float(h.b[1]));
    l.b[2] = __float2bfloat16_rn(v.z - __bfloat162float(h.b[2]));
    l.b[3] = __float2bfloat16_rn(v.w - __bfloat162float(h.b[3]));
    hi = h.u; lo = l.u;
}

__device__ __forceinline__ uint32_t packbf(float a, float b) {
    __nv_bfloat162 t = __floats2bfloat162_rn(a, b);
    return *(uint32_t*)&t;
}

// ===========================================================================
// Mask preprocess: int32 0/1 -> bf16 additive bias (0 or -1e9)
// ===========================================================================
__global__ __launch_bounds__(256) void maskprep_kernel(
    const int* __restrict__ mask, __nv_bfloat16* __restrict__ bias, int n8)
{
    const int i = blockIdx.x * 256 + threadIdx.x;
    if (i >= n8) return;
    int4 a = ((const int4*)mask)[i * 2];
    int4 b = ((const int4*)mask)[i * 2 + 1];
    const __nv_bfloat16 neg = __float2bfloat16_rn(-1e9f);
    const __nv_bfloat16 zer = __float2bfloat16_rn(0.0f);
    __nv_bfloat16 o[8];
    o[0] = (a.x == 0) ? neg : zer;
    o[1] = (a.y == 0) ? neg : zer;
    o[2] = (a.z == 0) ? neg : zer;
    o[3] = (a.w == 0) ? neg : zer;
    o[4] = (b.x == 0) ? neg : zer;
    o[5] = (b.y == 0) ? neg : zer;
    o[6] = (b.z == 0) ? neg : zer;
    o[7] = (b.w == 0) ? neg : zer;
    ((uint4*)bias)[i] = *(uint4*)o;
}

// ===========================================================================
// Split-bf16 mma.sync GEMM+bias (R12 version, unchanged — best measured).
// MODE 0: fp32 X in, bf16 hi/lo out (QKV projections, z batched)
// MODE 1: pre-split bf16 A in, fp32 out (final projection)
// ===========================================================================
#define BM 128
#define BN 128
#define BK 32

template<int MODE>
__global__ __launch_bounds__(256, 2) void gemm_mma_kernel(
    const float* __restrict__ X0, const float* __restrict__ X1, const float* __restrict__ X2,
    const __nv_bfloat16* __restrict__ Ah, const __nv_bfloat16* __restrict__ Al,
    const float* __restrict__ W0, const float* __restrict__ W1, const float* __restrict__ W2,
    const float* __restrict__ bias0, const float* __restrict__ bias1, const float* __restrict__ bias2,
    float* __restrict__ Yf,
    __nv_bfloat16* __restrict__ Yh0, __nv_bfloat16* __restrict__ Yh1, __nv_bfloat16* __restrict__ Yh2,
    __nv_bfloat16* __restrict__ Yl0, __nv_bfloat16* __restrict__ Yl1, __nv_bfloat16* __restrict__ Yl2)
{
    __shared__ __align__(128) __nv_bfloat16 sAh[BM * 40];
    __shared__ __align__(128) __nv_bfloat16 sAl[BM * 40];
    __shared__ __align__(128) __nv_bfloat16 sBh[BN * 40];
    __shared__ __align__(128) __nv_bfloat16 sBl[BN * 40];

    const int tid  = threadIdx.x;
    const int lane = tid & 31;
    const int wid  = tid >> 5;
    const int wm   = wid >> 2;
    const int wn   = wid & 3;
    const int m0 = blockIdx.y * BM;
    const int n0 = blockIdx.x * BN;
    const int z  = blockIdx.z;

    const float* X = (z == 0) ? X0 : (z == 1) ? X1 : X2;
    const float* W = (z == 0) ? W0 : (z == 1) ? W1 : W2;
    const float* bias = (z == 0) ? bias0 : (z == 1) ? bias1 : bias2;
    __nv_bfloat16* Yh = (z == 0) ? Yh0 : (z == 1) ? Yh1 : Yh2;
    __nv_bfloat16* Yl = (z == 0) ? Yl0 : (z == 1) ? Yl1 : Yl2;

    const uint32_t bAh = smem_u32(sAh);
    const uint32_t bAl = smem_u32(sAl);
    const uint32_t bBh = smem_u32(sBh);
    const uint32_t bBl = smem_u32(sBl);

    const uint32_t aoff = (uint32_t)((lane & 15) * 80 + (lane >> 4) * 16);
    const uint32_t boff = (uint32_t)(((lane & 7) + ((lane >> 4) & 1) * 8) * 80 +
                                     (((lane >> 3) & 1) ? 16 : 0));

    const int lr = tid >> 3;
    const int lc = tid & 7;

    float C[4][4][4];
#pragma unroll
    for (int i = 0; i < 4; i++)
#pragma unroll
        for (int j = 0; j < 4; j++)
#pragma unroll
            for (int t = 0; t < 4; t++) C[i][j][t] = 0.0f;

    for (int k0 = 0; k0 < D_; k0 += BK) {
        __syncthreads();
        if (MODE == 0) {
#pragma unroll
            for (int it = 0; it < 4; it++) {
                const int r = lr + it * 32;
                uint64_t hi, lo;
                float4 xv = *(const float4*)&X[(size_t)(m0 + r) * D_ + k0 + lc * 4];
                split4(xv, hi, lo);
                *(uint64_t*)((char*)sAh + r * 80 + lc * 8) = hi;
                *(uint64_t*)((char*)sAl + r * 80 + lc * 8) = lo;
            }
        } else {
#pragma unroll
            for (int i = 0; i < 2; i++) {
                const int idx = tid + i * 256;
                const int rr = idx >> 2;
                const int cc = idx & 3;
                const size_t g = (size_t)(m0 + rr) * D_ + k0 + cc * 8;
                *(uint4*)((char*)sAh + rr * 80 + cc * 16) = *(const uint4*)&Ah[g];
                *(uint4*)((char*)sAl + rr * 80 + cc * 16) = *(const uint4*)&Al[g];
            }
        }
#pragma unroll
        for (int it = 0; it < 4; it++) {
            const int r = lr + it * 32;
            uint64_t hi, lo;
            float4 wv = *(const float4*)&W[(size_t)(n0 + r) * D_ + k0 + lc * 4];
            split4(wv, hi, lo);
            *(uint64_t*)((char*)sBh + r * 80 + lc * 8) = hi;
            *(uint64_t*)((char*)sBl + r * 80 + lc * 8) = lo;
        }
        __syncthreads();

#pragma unroll
        for (int ks = 0; ks < 2; ks++) {
            const uint32_t kbyte = (uint32_t)(ks * 32);
            uint32_t bh[2][4], bl[2][4];
#pragma unroll
            for (int p = 0; p < 2; p++) {
                ldsm4(bh[p], bBh + (uint32_t)((wn * 32 + p * 16) * 80) + kbyte + boff);
                ldsm4(bl[p], bBl + (uint32_t)((wn * 32 + p * 16) * 80) + kbyte + boff);
            }
            {
                uint32_t a[4][4];
#pragma unroll
                for (int i = 0; i < 4; i++)
                    ldsm4(a[i], bAh + (uint32_t)((wm * 64 + i * 16) * 80) + kbyte + aoff);
#pragma unroll
                for (int i = 0; i < 4; i++)
#pragma unroll
                    for (int j = 0; j < 4; j++) {
                        mma16816(C[i][j], a[i][0], a[i][1], a[i][2], a[i][3],
                                 bh[j >> 1][(j & 1) * 2], bh[j >> 1][(j & 1) * 2 + 1]);
                        mma16816(C[i][j], a[i][0], a[i][1], a[i][2], a[i][3],
                                 bl[j >> 1][(j & 1) * 2], bl[j >> 1][(j & 1) * 2 + 1]);
                    }
            }
            {
                uint32_t a[4][4];
#pragma unroll
                for (int i = 0; i < 4; i++)
                    ldsm4(a[i], bAl + (uint32_t)((wm * 64 + i * 16) * 80) + kbyte + aoff);
#pragma unroll
                for (int i = 0; i < 4; i++)
#pragma unroll
                    for (int j = 0; j < 4; j++)
                        mma16816(C[i][j], a[i][0], a[i][1], a[i][2], a[i][3],
                                 bh[j >> 1][(j & 1) * 2], bh[j >> 1][(j & 1) * 2 + 1]);
            }
        }
    }

    const int qr = lane >> 2;
    const int qc = (lane & 3) * 2;
#pragma unroll
    for (int i = 0; i < 4; i++) {
        const int row0 = m0 + wm * 64 + i * 16 + qr;
#pragma unroll
        for (int j = 0; j < 4; j++) {
            const int col = n0 + wn * 32 + j * 8 + qc;
            const float b0v = bias[col], b1v = bias[col + 1];
            float v0 = C[i][j][0] + b0v, v1 = C[i][j][1] + b1v;
            float v2 = C[i][j][2] + b0v, v3 = C[i][j][3] + b1v;
            if (MODE == 0) {
                __nv_bfloat16 h0 = __float2bfloat16_rn(v0);
                __nv_bfloat16 h1 = __float2bfloat16_rn(v1);
                __nv_bfloat16 h2 = __float2bfloat16_rn(v2);
                __nv_bfloat16 h3 = __float2bfloat16_rn(v3);
                __nv_bfloat162 hp0; hp0.x = h0; hp0.y = h1;
                __nv_bfloat162 hp1; hp1.x = h2; hp1.y = h3;
                *(uint32_t*)&Yh[(size_t)row0 * D_ + col]       = *(uint32_t*)&hp0;
                *(uint32_t*)&Yh[(size_t)(row0 + 8) * D_ + col] = *(uint32_t*)&hp1;
                *(uint32_t*)&Yl[(size_t)row0 * D_ + col] =
                    packbf(v0 - __bfloat162float(h0), v1 - __bfloat162float(h1));
                *(uint32_t*)&Yl[(size_t)(row0 + 8) * D_ + col] =
                    packbf(v2 - __bfloat162float(h2), v3 - __bfloat162float(h3));
            } else {
                float2 o0 = { v0, v1 };
                float2 o1 = { v2, v3 };
                *(float2*)&Yf[(size_t)row0 * D_ + col]       = o0;
                *(float2*)&Yf[(size_t)(row0 + 8) * D_ + col] = o1;
            }
        }
    }
}

// ===========================================================================
// Flash attention — R12 body; mask applied as bf16 additive bias via FMA.
// ===========================================================================
#define ATQ 128
#define ATK 64
#define ALD 144

#define AOFF_QH 0
#define AOFF_QL (AOFF_QH + ATQ * ALD)
#define AOFF_KH (AOFF_QL + ATQ * ALD)
#define AOFF_KL (AOFF_KH + ATK * ALD)
#define AOFF_VH (AOFF_KL + ATK * ALD)
#define AOFF_VL (AOFF_VH + ATK * ALD)
#define ATTN_SMEM_BYTES (AOFF_VL + ATK * ALD)  // 73728

__global__ __launch_bounds__(256, 2) void attn_mma_kernel(
    const __nv_bfloat16* __restrict__ Qh, const __nv_bfloat16* __restrict__ Ql,
    const __nv_bfloat16* __restrict__ Kh, const __nv_bfloat16* __restrict__ Kl,
    const __nv_bfloat16* __restrict__ Vh, const __nv_bfloat16* __restrict__ Vl,
    const __nv_bfloat16* __restrict__ Bias,
    __nv_bfloat16* __restrict__ Ch, __nv_bfloat16* __restrict__ Cl)
{
    extern __shared__ __align__(128) char smem[];
    const uint32_t sb = smem_u32(smem);

    const int tid  = threadIdx.x;
    const int lane = tid & 31;
    const int wid  = tid >> 5;
    const int bh = blockIdx.y;
    const int b  = bh >> 4;
    const int h  = bh & 15;
    const int q0 = blockIdx.x * ATQ;

    const size_t base = (size_t)b * S_ * D_ + (size_t)h * DK_;
    const __nv_bfloat16* Qhb = Qh + base;
    const __nv_bfloat16* Qlb = Ql + base;
    const __nv_bfloat16* Khb = Kh + base;
    const __nv_bfloat16* Klb = Kl + base;
    const __nv_bfloat16* Vhb = Vh + base;
    const __nv_bfloat16* Vlb = Vl + base;

    // ---- load Q tile ----
#pragma unroll
    for (int i = 0; i < 4; i++) {
        const int idx = tid + i * 256;
        const int rr = idx >> 3;
        const int cc = idx & 7;
        *(uint4*)(smem + AOFF_QH + rr * ALD + cc * 16) =
            *(const uint4*)&Qhb[(size_t)(q0 + rr) * D_ + cc * 8];
        *(uint4*)(smem + AOFF_QL + rr * ALD + cc * 16) =
            *(const uint4*)&Qlb[(size_t)(q0 + rr) * D_ + cc * 8];
    }

    const uint32_t aoffQ = sb + (uint32_t)((wid * 16 + (lane & 15)) * ALD + (lane >> 4) * 16);
    const uint32_t boffK = sb + (uint32_t)(((lane & 7) + ((lane >> 4) & 1) * 8) * ALD +
                                           ((lane >> 3) & 1) * 16);
    const uint32_t voffV = sb + (uint32_t)((((lane >> 3) & 1) * 8 + (lane & 7)) * ALD +
                                           ((lane >> 4) & 1) * 16);

    float mstate[2] = { -1e30f, -1e30f };
    float lstate[2] = { 0.0f, 0.0f };
    float O[8][4];
#pragma unroll
    for (int j = 0; j < 8; j++)
#pragma unroll
        for (int t = 0; t < 4; t++) O[j][t] = 0.0f;

    const int row0 = q0 + wid * 16 + (lane >> 2);
    const int mcol = (lane & 3) * 2;
    const __nv_bfloat16* brow0 = Bias + (size_t)b * S_ * S_ + (size_t)row0 * S_;
    const __nv_bfloat16* brow1 = brow0 + (size_t)8 * S_;

    for (int k0 = 0; k0 < S_; k0 += ATK) {
        __syncthreads();
        // ---- load K,V tiles ----
#pragma unroll
        for (int i = 0; i < 2; i++) {
            const int idx = tid + i * 256;
            const int rr = idx >> 3;
            const int cc = idx & 7;
            const size_t g = (size_t)(k0 + rr) * D_ + cc * 8;
            *(uint4*)(smem + AOFF_KH + rr * ALD + cc * 16) = *(const uint4*)&Khb[g];
            *(uint4*)(smem + AOFF_KL + rr * ALD + cc * 16) = *(const uint4*)&Klb[g];
            *(uint4*)(smem + AOFF_VH + rr * ALD + cc * 16) = *(const uint4*)&Vhb[g];
            *(uint4*)(smem + AOFF_VL + rr * ALD + cc * 16) = *(const uint4*)&Vlb[g];
        }
        __syncthreads();

        // ---- S = Q K^T (split compensated) ----
        float Sf[8][4];
#pragma unroll
        for (int j = 0; j < 8; j++)
#pragma unroll
            for (int tt = 0; tt < 4; tt++) Sf[j][tt] = 0.0f;

#pragma unroll
        for (int kc = 0; kc < 4; kc++) {
            const uint32_t kb = (uint32_t)(kc * 32);
            uint32_t ah[4], al[4];
            ldsm4(ah, aoffQ + AOFF_QH + kb);
            ldsm4(al, aoffQ + AOFF_QL + kb);
#pragma unroll
            for (int jp = 0; jp < 4; jp++) {
                uint32_t kh[4], kl[4];
                ldsm4(kh, boffK + AOFF_KH + (uint32_t)(jp * 16 * ALD) + kb);
                ldsm4(kl, boffK + AOFF_KL + (uint32_t)(jp * 16 * ALD) + kb);
                mma16816(Sf[jp * 2],     ah[0], ah[1], ah[2], ah[3], kh[0], kh[1]);
                mma16816(Sf[jp * 2],     ah[0], ah[1], ah[2], ah[3], kl[0], kl[1]);
                mma16816(Sf[jp * 2],     al[0], al[1], al[2], al[3], kh[0], kh[1]);
                mma16816(Sf[jp * 2 + 1], ah[0], ah[1], ah[2], ah[3], kh[2], kh[3]);
                mma16816(Sf[jp * 2 + 1], ah[0], ah[1], ah[2], ah[3], kl[2], kl[3]);
                mma16816(Sf[jp * 2 + 1], al[0], al[1], al[2], al[3], kh[2], kh[3]);
            }
        }

        // ---- scale + mask (additive bf16 bias via FMA) ----
#pragma unroll
        for (int j = 0; j < 8; j++) {
            const uint32_t t0 = *(const uint32_t*)&brow0[k0 + j * 8 + mcol];
            const uint32_t t1 = *(const uint32_t*)&brow1[k0 + j * 8 + mcol];
            const __nv_bfloat162 bb0 = *(const __nv_bfloat162*)&t0;
            const __nv_bfloat162 bb1 = *(const __nv_bfloat162*)&t1;
            Sf[j][0] = fmaf(Sf[j][0], 0.125f, __bfloat162float(bb0.x));
            Sf[j][1] = fmaf(Sf[j][1], 0.125f, __bfloat162float(bb0.y));
            Sf[j][2] = fmaf(Sf[j][2], 0.125f, __bfloat162float(bb1.x));
            Sf[j][3] = fmaf(Sf[j][3], 0.125f, __bfloat162float(bb1.y));
        }

        // ---- online softmax ----
        float corr[2];
#pragma unroll
        for (int rr = 0; rr < 2; rr++) {
            float mx = -1e30f;
#pragma unroll
            for (int j = 0; j < 8; j++)
                mx = fmaxf(mx, fmaxf(Sf[j][rr * 2], Sf[j][rr * 2 + 1]));
            mx = fmaxf(mx, __shfl_xor_sync(0xFFFFFFFF, mx, 1));
            mx = fmaxf(mx, __shfl_xor_sync(0xFFFFFFFF, mx, 2));
            float mnew = fmaxf(mstate[rr], mx);
            corr[rr] = __expf(mstate[rr] - mnew);
            float sum = 0.0f;
#pragma unroll
            for (int j = 0; j < 8; j++) {
                float p0 = __expf(Sf[j][rr * 2]     - mnew);
                float p1 = __expf(Sf[j][rr * 2 + 1] - mnew);
                Sf[j][rr * 2] = p0; Sf[j][rr * 2 + 1] = p1;
                sum += p0 + p1;
            }
            sum += __shfl_xor_sync(0xFFFFFFFF, sum, 1);
            sum += __shfl_xor_sync(0xFFFFFFFF, sum, 2);
            lstate[rr] = lstate[rr] * corr[rr] + sum;
            mstate[rr] = mnew;
        }

#pragma unroll
        for (int j = 0; j < 8; j++) {
            O[j][0] *= corr[0]; O[j][1] *= corr[0];
            O[j][2] *= corr[1]; O[j][3] *= corr[1];
        }

        // ---- pack P (hi/lo split) ----
        uint32_t aPh[4][4], aPl[4][4];
#pragma unroll
        for (int kc = 0; kc < 4; kc++) {
#pragma unroll
            for (int half = 0; half < 2; half++) {
                const int j = kc * 2 + half;
#pragma unroll
                for (int rr = 0; rr < 2; rr++) {
                    float p0 = Sf[j][rr * 2], p1 = Sf[j][rr * 2 + 1];
                    __nv_bfloat16 h0 = __float2bfloat16_rn(p0);
                    __nv_bfloat16 h1 = __float2bfloat16_rn(p1);
                    __nv_bfloat162 hp; hp.x = h0; hp.y = h1;
                    aPh[kc][half * 2 + rr] = *(uint32_t*)&hp;
                    aPl[kc][half * 2 + rr] =
                        packbf(p0 - __bfloat162float(h0), p1 - __bfloat162float(h1));
                }
            }
        }

        // ---- O += P V (split compensated) ----
#pragma unroll
        for (int kc = 0; kc < 4; kc++) {
#pragma unroll
            for (int jp = 0; jp < 4; jp++) {
                uint32_t vh[4], vl[4];
                ldsm4t(vh, voffV + AOFF_VH + (uint32_t)(kc * 16 * ALD) + (uint32_t)(jp * 32));
                ldsm4t(vl, voffV + AOFF_VL + (uint32_t)(kc * 16 * ALD) + (uint32_t)(jp * 32));
                mma16816(O[jp * 2],     aPh[kc][0], aPh[kc][1], aPh[kc][2], aPh[kc][3], vh[0], vh[1]);
                mma16816(O[jp * 2],     aPh[kc][0], aPh[kc][1], aPh[kc][2], aPh[kc][3], vl[0], vl[1]);
                mma16816(O[jp * 2],     aPl[kc][0], aPl[kc][1], aPl[kc][2], aPl[kc][3], vh[0], vh[1]);
                mma16816(O[jp * 2 + 1], aPh[kc][0], aPh[kc][1], aPh[kc][2], aPh[kc][3], vh[2], vh[3]);
                mma16816(O[jp * 2 + 1], aPh[kc][0], aPh[kc][1], aPh[kc][2], aPh[kc][3], vl[2], vl[3]);
                mma16816(O[jp * 2 + 1], aPl[kc][0], aPl[kc][1], aPl[kc][2], aPl[kc][3], vh[2], vh[3]);
            }
        }
        __syncthreads();
    }

    // ---- finalize: write pre-split context ----
    const float inv0 = 1.0f / lstate[0];
    const float inv1 = 1.0f / lstate[1];
    __nv_bfloat16* Chb = Ch + base;
    __nv_bfloat16* Clb = Cl + base;
#pragma unroll
    for (int j = 0; j < 8; j++) {
        const int col = j * 8 + mcol;
        float v0 = O[j][0] * inv0, v1 = O[j][1] * inv0;
        float v2 = O[j][2] * inv1, v3 = O[j][3] * inv1;
        __nv_bfloat16 h0 = __float2bfloat16_rn(v0);
        __nv_bfloat16 h1 = __float2bfloat16_rn(v1);
        __nv_bfloat16 h2 = __float2bfloat16_rn(v2);
        __nv_bfloat16 h3 = __float2bfloat16_rn(v3);
        __nv_bfloat162 hp0; hp0.x = h0; hp0.y = h1;
        __nv_bfloat162 hp1; hp1.x = h2; hp1.y = h3;
        *(uint32_t*)&Chb[(size_t)row0 * D_ + col]       = *(uint32_t*)&hp0;
        *(uint32_t*)&Chb[(size_t)(row0 + 8) * D_ + col] = *(uint32_t*)&hp1;
        *(uint32_t*)&Clb[(size_t)row0 * D_ + col] =
            packbf(v0 - __bfloat162float(h0), v1 - __bfloat162float(h1));
        *(uint32_t*)&Clb[(size_t)(row0 + 8) * D_ + col] =
            packbf(v2 - __bfloat162float(h2), v3 - __bfloat162float(h3));
    }
}

// ---------------------------------------------------------------------------
// Launch
// ---------------------------------------------------------------------------
extern "C" void kernel_launch(void* const* d_in, const int* in_sizes, int n_in,
                              void* d_out, int out_size)
{
    (void)in_sizes; (void)n_in; (void)out_size;
    const float* q    = (const float*)d_in[0];
    const float* k    = (const float*)d_in[1];
    const float* v    = (const float*)d_in[2];
    const int*   mask = (const int*)d_in[3];
    const float* w_q  = (const float*)d_in[4];
    const float* b_q  = (const float*)d_in[5];
    const float* w_k  = (const float*)d_in[6];
    const float* b_k  = (const float*)d_in[7];
    const float* w_v  = (const float*)d_in[8];
    const float* b_v  = (const float*)d_in[9];
    const float* w_o  = (const float*)d_in[10];
    const float* b_o  = (const float*)d_in[11];
    float* out = (float*)d_out;

    __nv_bfloat16 *gQh, *gQl, *gKh, *gKl, *gVh, *gVl, *gCh, *gCl, *gBias;
    cudaGetSymbolAddress((void**)&gQh, g_Qh);
    cudaGetSymbolAddress((void**)&gQl, g_Ql);
    cudaGetSymbolAddress((void**)&gKh, g_Kh);
    cudaGetSymbolAddress((void**)&gKl, g_Kl);
    cudaGetSymbolAddress((void**)&gVh, g_Vh);
    cudaGetSymbolAddress((void**)&gVl, g_Vl);
    cudaGetSymbolAddress((void**)&gCh, g_Ch);
    cudaGetSymbolAddress((void**)&gCl, g_Cl);
    cudaGetSymbolAddress((void**)&gBias, g_Bias);

    cudaFuncSetAttribute(attn_mma_kernel,
                         cudaFuncAttributeMaxDynamicSharedMemorySize,
                         ATTN_SMEM_BYTES);

    dim3 gblk(256);

    // mask -> bf16 additive bias (runs concurrently-independent of projections)
    const int n8 = (B_ * S_ * S_) / 8;    // 1,048,576
    maskprep_kernel<<<(n8 + 255) / 256, 256>>>(mask, gBias, n8);

    // Q/K/V projections batched over z
    dim3 ggrid3(D_ / BN, M_ / BM, 3);
    gemm_mma_kernel<0><<<ggrid3, gblk>>>(
        q, k, v, nullptr, nullptr,
        w_q, w_k, w_v, b_q, b_k, b_v,
        nullptr,
        gQh, gKh, gVh, gQl, gKl, gVl);

    dim3 ablk(256);
    dim3 agrid(S_ / ATQ, B_ * H_);    // (16, 32)
    attn_mma_kernel<<<agrid, ablk, ATTN_SMEM_BYTES>>>(
        gQh, gQl, gKh, gKl, gVh, gVl, gBias, gCh, gCl);

    // final projection (pre-split A)
    dim3 ggrid1(D_ / BN, M_ / BM, 1);
    gemm_mma_kernel<1><<<ggrid1, gblk>>>(
        nullptr, nullptr, nullptr, gCh, gCl,
        w_o, nullptr, nullptr, b_o, nullptr, nullptr,
        out,
        nullptr, nullptr, nullptr, nullptr, nullptr, nullptr);
}

// round 14
// speedup vs baseline: 1.0258x; 1.0258x over previous
#include <cuda_runtime.h>
#include <cuda_bf16.h>
#include <cstdint>

// Problem constants
#define B_  2
#define S_  2048
#define D_  1024
#define H_  16
#define DK_ 64
#define M_  (B_ * S_)   // 4096

#define NSM   148
#define NPERS (NSM * 2)   // persistent grid: 2 CTAs/SM

// ---------------------------------------------------------------------------
// Scratch
// ---------------------------------------------------------------------------
__device__ __nv_bfloat16 g_Qh[M_ * D_];
__device__ __nv_bfloat16 g_Ql[M_ * D_];
__device__ __nv_bfloat16 g_Kh[M_ * D_];
__device__ __nv_bfloat16 g_Kl[M_ * D_];
__device__ __nv_bfloat16 g_Vh[M_ * D_];
__device__ __nv_bfloat16 g_Vl[M_ * D_];
__device__ __nv_bfloat16 g_Ch[M_ * D_];
__device__ __nv_bfloat16 g_Cl[M_ * D_];

__device__ __forceinline__ uint32_t smem_u32(const void* p) {
    uint32_t a;
    asm("{ .reg .u64 t; cvta.to.shared.u64 t, %1; cvt.u32.u64 %0, t; }"
        : "=r"(a) : "l"(p));
    return a;
}

__device__ __forceinline__ void mma16816(float* c,
                                         uint32_t a0, uint32_t a1, uint32_t a2, uint32_t a3,
                                         uint32_t b0, uint32_t b1) {
    asm volatile(
        "mma.sync.aligned.m16n8k16.row.col.f32.bf16.bf16.f32 "
        "{%0,%1,%2,%3}, {%4,%5,%6,%7}, {%8,%9}, {%0,%1,%2,%3};"
        : "+f"(c[0]), "+f"(c[1]), "+f"(c[2]), "+f"(c[3])
        : "r"(a0), "r"(a1), "r"(a2), "r"(a3), "r"(b0), "r"(b1));
}

__device__ __forceinline__ void ldsm4(uint32_t* r, uint32_t addr) {
    asm volatile("ldmatrix.sync.aligned.m8n8.x4.shared.b16 {%0,%1,%2,%3}, [%4];"
                 : "=r"(r[0]), "=r"(r[1]), "=r"(r[2]), "=r"(r[3]) : "r"(addr));
}

__device__ __forceinline__ void ldsm4t(uint32_t* r, uint32_t addr) {
    asm volatile("ldmatrix.sync.aligned.m8n8.x4.trans.shared.b16 {%0,%1,%2,%3}, [%4];"
                 : "=r"(r[0]), "=r"(r[1]), "=r"(r[2]), "=r"(r[3]) : "r"(addr));
}

union PackB4 { uint64_t u; __nv_bfloat16 b[4]; };

__device__ __forceinline__ void split4(float4 v, uint64_t& hi, uint64_t& lo) {
    PackB4 h, l;
    h.b[0] = __float2bfloat16_rn(v.x);
    h.b[1] = __float2bfloat16_rn(v.y);
    h.b[2] = __float2bfloat16_rn(v.z);
    h.b[3] = __float2bfloat16_rn(v.w);
    l.b[0] = __float2bfloat16_rn(v.x - __bfloat162float(h.b[0]));
    l.b[1] = __float2bfloat16_rn(v.y - __bfloat162float(h.b[1]));
    l.b[2] = __float2bfloat16_rn(v.z - __bfloat162float(h.b[2]));
    l.b[3] = __float2bfloat16_rn(v.w - __bfloat162float(h.b[3]));
    hi = h.u; lo = l.u;
}

__device__ __forceinline__ uint32_t packbf(float a, float b) {
    __nv_bfloat162 t = __floats2bfloat162_rn(a, b);
    return *(uint32_t*)&t;
}

// ===========================================================================
// Split-bf16 mma.sync GEMM+bias — R12 body, persistent tile loop.
// MODE 0: fp32 X in, bf16 hi/lo out (QKV projections; 768 tiles over z,m,n)
// MODE 1: pre-split bf16 A in, fp32 out (256 tiles; grid < NPERS, 1 tile each)
// ===========================================================================
#define BM 128
#define BN 128
#define BK 32

template<int MODE>
__global__ __launch_bounds__(256, 2) void gemm_mma_kernel(
    const float* __restrict__ X0, const float* __restrict__ X1, const float* __restrict__ X2,
    const __nv_bfloat16* __restrict__ Ah, const __nv_bfloat16* __restrict__ Al,
    const float* __restrict__ W0, const float* __restrict__ W1, const float* __restrict__ W2,
    const float* __restrict__ bias0, const float* __restrict__ bias1, const float* __restrict__ bias2,
    float* __restrict__ Yf,
    __nv_bfloat16* __restrict__ Yh0, __nv_bfloat16* __restrict__ Yh1, __nv_bfloat16* __restrict__ Yh2,
    __nv_bfloat16* __restrict__ Yl0, __nv_bfloat16* __restrict__ Yl1, __nv_bfloat16* __restrict__ Yl2,
    int ntiles)
{
    __shared__ __align__(128) __nv_bfloat16 sAh[BM * 40];
    __shared__ __align__(128) __nv_bfloat16 sAl[BM * 40];
    __shared__ __align__(128) __nv_bfloat16 sBh[BN * 40];
    __shared__ __align__(128) __nv_bfloat16 sBl[BN * 40];

    const int tid  = threadIdx.x;
    const int lane = tid & 31;
    const int wid  = tid >> 5;
    const int wm   = wid >> 2;
    const int wn   = wid & 3;

    const uint32_t bAh = smem_u32(sAh);
    const uint32_t bAl = smem_u32(sAl);
    const uint32_t bBh = smem_u32(sBh);
    const uint32_t bBl = smem_u32(sBl);

    const uint32_t aoff = (uint32_t)((lane & 15) * 80 + (lane >> 4) * 16);
    const uint32_t boff = (uint32_t)(((lane & 7) + ((lane >> 4) & 1) * 8) * 80 +
                                     (((lane >> 3) & 1) ? 16 : 0));

    const int lr = tid >> 3;
    const int lc = tid & 7;
    const int qr = lane >> 2;
    const int qc = (lane & 3) * 2;

    // persistent tile loop: tiles laid out as (z, m, n): tile = (z*32 + my)*8 + nx
    for (int tile = blockIdx.x; tile < ntiles; tile += gridDim.x) {
        const int nx = tile & 7;                 // 0..7
        const int my = (tile >> 3) & 31;         // 0..31
        const int z  = tile >> 8;                // 0..2 (MODE 0) / 0 (MODE 1)
        const int m0 = my * BM;
        const int n0 = nx * BN;

        const float* X = (z == 0) ? X0 : (z == 1) ? X1 : X2;
        const float* W = (z == 0) ? W0 : (z == 1) ? W1 : W2;
        const float* bias = (z == 0) ? bias0 : (z == 1) ? bias1 : bias2;
        __nv_bfloat16* Yh = (z == 0) ? Yh0 : (z == 1) ? Yh1 : Yh2;
        __nv_bfloat16* Yl = (z == 0) ? Yl0 : (z == 1) ? Yl1 : Yl2;

        float C[4][4][4];
#pragma unroll
        for (int i = 0; i < 4; i++)
#pragma unroll
            for (int j = 0; j < 4; j++)
#pragma unroll
                for (int t = 0; t < 4; t++) C[i][j][t] = 0.0f;

        for (int k0 = 0; k0 < D_; k0 += BK) {
            __syncthreads();
            if (MODE == 0) {
#pragma unroll
                for (int it = 0; it < 4; it++) {
                    const int r = lr + it * 32;
                    uint64_t hi, lo;
                    float4 xv = *(const float4*)&X[(size_t)(m0 + r) * D_ + k0 + lc * 4];
                    split4(xv, hi, lo);
                    *(uint64_t*)((char*)sAh + r * 80 + lc * 8) = hi;
                    *(uint64_t*)((char*)sAl + r * 80 + lc * 8) = lo;
                }
            } else {
#pragma unroll
                for (int i = 0; i < 2; i++) {
                    const int idx = tid + i * 256;
                    const int rr = idx >> 2;
                    const int cc = idx & 3;
                    const size_t g = (size_t)(m0 + rr) * D_ + k0 + cc * 8;
                    *(uint4*)((char*)sAh + rr * 80 + cc * 16) = *(const uint4*)&Ah[g];
                    *(uint4*)((char*)sAl + rr * 80 + cc * 16) = *(const uint4*)&Al[g];
                }
            }
#pragma unroll
            for (int it = 0; it < 4; it++) {
                const int r = lr + it * 32;
                uint64_t hi, lo;
                float4 wv = *(const float4*)&W[(size_t)(n0 + r) * D_ + k0 + lc * 4];
                split4(wv, hi, lo);
                *(uint64_t*)((char*)sBh + r * 80 + lc * 8) = hi;
                *(uint64_t*)((char*)sBl + r * 80 + lc * 8) = lo;
            }
            __syncthreads();

#pragma unroll
            for (int ks = 0; ks < 2; ks++) {
                const uint32_t kbyte = (uint32_t)(ks * 32);
                uint32_t bh[2][4], bl[2][4];
#pragma unroll
                for (int p = 0; p < 2; p++) {
                    ldsm4(bh[p], bBh + (uint32_t)((wn * 32 + p * 16) * 80) + kbyte + boff);
                    ldsm4(bl[p], bBl + (uint32_t)((wn * 32 + p * 16) * 80) + kbyte + boff);
                }
                {
                    uint32_t a[4][4];
#pragma unroll
                    for (int i = 0; i < 4; i++)
                        ldsm4(a[i], bAh + (uint32_t)((wm * 64 + i * 16) * 80) + kbyte + aoff);
#pragma unroll
                    for (int i = 0; i < 4; i++)
#pragma unroll
                        for (int j = 0; j < 4; j++) {
                            mma16816(C[i][j], a[i][0], a[i][1], a[i][2], a[i][3],
                                     bh[j >> 1][(j & 1) * 2], bh[j >> 1][(j & 1) * 2 + 1]);
                            mma16816(C[i][j], a[i][0], a[i][1], a[i][2], a[i][3],
                                     bl[j >> 1][(j & 1) * 2], bl[j >> 1][(j & 1) * 2 + 1]);
                        }
                }
                {
                    uint32_t a[4][4];
#pragma unroll
                    for (int i = 0; i < 4; i++)
                        ldsm4(a[i], bAl + (uint32_t)((wm * 64 + i * 16) * 80) + kbyte + aoff);
#pragma unroll
                    for (int i = 0; i < 4; i++)
#pragma unroll
                        for (int j = 0; j < 4; j++)
                            mma16816(C[i][j], a[i][0], a[i][1], a[i][2], a[i][3],
                                     bh[j >> 1][(j & 1) * 2], bh[j >> 1][(j & 1) * 2 + 1]);
                }
            }
        }

#pragma unroll
        for (int i = 0; i < 4; i++) {
            const int row0 = m0 + wm * 64 + i * 16 + qr;
#pragma unroll
            for (int j = 0; j < 4; j++) {
                const int col = n0 + wn * 32 + j * 8 + qc;
                const float b0v = bias[col], b1v = bias[col + 1];
                float v0 = C[i][j][0] + b0v, v1 = C[i][j][1] + b1v;
                float v2 = C[i][j][2] + b0v, v3 = C[i][j][3] + b1v;
                if (MODE == 0) {
                    __nv_bfloat16 h0 = __float2bfloat16_rn(v0);
                    __nv_bfloat16 h1 = __float2bfloat16_rn(v1);
                    __nv_bfloat16 h2 = __float2bfloat16_rn(v2);
                    __nv_bfloat16 h3 = __float2bfloat16_rn(v3);
                    __nv_bfloat162 hp0; hp0.x = h0; hp0.y = h1;
                    __nv_bfloat162 hp1; hp1.x = h2; hp1.y = h3;
                    *(uint32_t*)&Yh[(size_t)row0 * D_ + col]       = *(uint32_t*)&hp0;
                    *(uint32_t*)&Yh[(size_t)(row0 + 8) * D_ + col] = *(uint32_t*)&hp1;
                    *(uint32_t*)&Yl[(size_t)row0 * D_ + col] =
                        packbf(v0 - __bfloat162float(h0), v1 - __bfloat162float(h1));
                    *(uint32_t*)&Yl[(size_t)(row0 + 8) * D_ + col] =
                        packbf(v2 - __bfloat162float(h2), v3 - __bfloat162float(h3));
                } else {
                    float2 o0 = { v0, v1 };
                    float2 o1 = { v2, v3 };
                    *(float2*)&Yf[(size_t)row0 * D_ + col]       = o0;
                    *(float2*)&Yf[(size_t)(row0 + 8) * D_ + col] = o1;
                }
            }
        }
        __syncthreads();   // smem safe before next tile overwrites
    }
}

// ===========================================================================
// Flash attention — R12 body (int mask, best measured), persistent tile loop.
// 512 logical tiles: (q-block 0..15) x (b,h 0..31).
// ===========================================================================
#define ATQ 128
#define ATK 64
#define ALD 144

#define AOFF_QH 0
#define AOFF_QL (AOFF_QH + ATQ * ALD)
#define AOFF_KH (AOFF_QL + ATQ * ALD)
#define AOFF_KL (AOFF_KH + ATK * ALD)
#define AOFF_VH (AOFF_KL + ATK * ALD)
#define AOFF_VL (AOFF_VH + ATK * ALD)
#define ATTN_SMEM_BYTES (AOFF_VL + ATK * ALD)  // 73728

__global__ __launch_bounds__(256, 2) void attn_mma_kernel(
    const __nv_bfloat16* __restrict__ Qh, const __nv_bfloat16* __restrict__ Ql,
    const __nv_bfloat16* __restrict__ Kh, const __nv_bfloat16* __restrict__ Kl,
    const __nv_bfloat16* __restrict__ Vh, const __nv_bfloat16* __restrict__ Vl,
    const int* __restrict__ mask,
    __nv_bfloat16* __restrict__ Ch, __nv_bfloat16* __restrict__ Cl)
{
    extern __shared__ __align__(128) char smem[];
    const uint32_t sb = smem_u32(smem);

    const int tid  = threadIdx.x;
    const int lane = tid & 31;
    const int wid  = tid >> 5;

    const uint32_t aoffQ = sb + (uint32_t)((wid * 16 + (lane & 15)) * ALD + (lane >> 4) * 16);
    const uint32_t boffK = sb + (uint32_t)(((lane & 7) + ((lane >> 4) & 1) * 8) * ALD +
                                           ((lane >> 3) & 1) * 16);
    const uint32_t voffV = sb + (uint32_t)((((lane >> 3) & 1) * 8 + (lane & 7)) * ALD +
                                           ((lane >> 4) & 1) * 16);
    const int mcol = (lane & 3) * 2;

    const int NTILES = (S_ / ATQ) * B_ * H_;   // 512

    for (int tile = blockIdx.x; tile < NTILES; tile += gridDim.x) {
        const int qb = tile & 15;         // 0..15 q-block
        const int bh = tile >> 4;         // 0..31
        const int b  = bh >> 4;
        const int h  = bh & 15;
        const int q0 = qb * ATQ;

        const size_t base = (size_t)b * S_ * D_ + (size_t)h * DK_;
        const __nv_bfloat16* Qhb = Qh + base;
        const __nv_bfloat16* Qlb = Ql + base;
        const __nv_bfloat16* Khb = Kh + base;
        const __nv_bfloat16* Klb = Kl + base;
        const __nv_bfloat16* Vhb = Vh + base;
        const __nv_bfloat16* Vlb = Vl + base;
        const int* Mb = mask + (size_t)b * S_ * S_;

        __syncthreads();   // previous tile's smem reads complete
        // ---- load Q tile ----
#pragma unroll
        for (int i = 0; i < 4; i++) {
            const int idx = tid + i * 256;
            const int rr = idx >> 3;
            const int cc = idx & 7;
            *(uint4*)(smem + AOFF_QH + rr * ALD + cc * 16) =
                *(const uint4*)&Qhb[(size_t)(q0 + rr) * D_ + cc * 8];
            *(uint4*)(smem + AOFF_QL + rr * ALD + cc * 16) =
                *(const uint4*)&Qlb[(size_t)(q0 + rr) * D_ + cc * 8];
        }

        float mstate[2] = { -1e30f, -1e30f };
        float lstate[2] = { 0.0f, 0.0f };
        float O[8][4];
#pragma unroll
        for (int j = 0; j < 8; j++)
#pragma unroll
            for (int t = 0; t < 4; t++) O[j][t] = 0.0f;

        const int row0 = q0 + wid * 16 + (lane >> 2);
        const int* mrow0 = Mb + (size_t)row0 * S_;
        const int* mrow1 = Mb + (size_t)(row0 + 8) * S_;

        for (int k0 = 0; k0 < S_; k0 += ATK) {
            __syncthreads();
            // ---- load K,V tiles ----
#pragma unroll
            for (int i = 0; i < 2; i++) {
                const int idx = tid + i * 256;
                const int rr = idx >> 3;
                const int cc = idx & 7;
                const size_t g = (size_t)(k0 + rr) * D_ + cc * 8;
                *(uint4*)(smem + AOFF_KH + rr * ALD + cc * 16) = *(const uint4*)&Khb[g];
                *(uint4*)(smem + AOFF_KL + rr * ALD + cc * 16) = *(const uint4*)&Klb[g];
                *(uint4*)(smem + AOFF_VH + rr * ALD + cc * 16) = *(const uint4*)&Vhb[g];
                *(uint4*)(smem + AOFF_VL + rr * ALD + cc * 16) = *(const uint4*)&Vlb[g];
            }
            __syncthreads();

            // ---- S = Q K^T (split compensated) ----
            float Sf[8][4];
#pragma unroll
            for (int j = 0; j < 8; j++)
#pragma unroll
                for (int tt = 0; tt < 4; tt++) Sf[j][tt] = 0.0f;

#pragma unroll
            for (int kc = 0; kc < 4; kc++) {
                const uint32_t kb = (uint32_t)(kc * 32);
                uint32_t ah[4], al[4];
                ldsm4(ah, aoffQ + AOFF_QH + kb);
                ldsm4(al, aoffQ + AOFF_QL + kb);
#pragma unroll
                for (int jp = 0; jp < 4; jp++) {
                    uint32_t kh[4], kl[4];
                    ldsm4(kh, boffK + AOFF_KH + (uint32_t)(jp * 16 * ALD) + kb);
                    ldsm4(kl, boffK + AOFF_KL + (uint32_t)(jp * 16 * ALD) + kb);
                    mma16816(Sf[jp * 2],     ah[0], ah[1], ah[2], ah[3], kh[0], kh[1]);
                    mma16816(Sf[jp * 2],     ah[0], ah[1], ah[2], ah[3], kl[0], kl[1]);
                    mma16816(Sf[jp * 2],     al[0], al[1], al[2], al[3], kh[0], kh[1]);
                    mma16816(Sf[jp * 2 + 1], ah[0], ah[1], ah[2], ah[3], kh[2], kh[3]);
                    mma16816(Sf[jp * 2 + 1], ah[0], ah[1], ah[2], ah[3], kl[2], kl[3]);
                    mma16816(Sf[jp * 2 + 1], al[0], al[1], al[2], al[3], kh[2], kh[3]);
                }
            }

            // ---- scale + mask ----
#pragma unroll
            for (int j = 0; j < 8; j++) {
                int2 mv0 = *(const int2*)&mrow0[k0 + j * 8 + mcol];
                int2 mv1 = *(const int2*)&mrow1[k0 + j * 8 + mcol];
                Sf[j][0] = (mv0.x == 0) ? -1e9f : Sf[j][0] * 0.125f;
                Sf[j][1] = (mv0.y == 0) ? -1e9f : Sf[j][1] * 0.125f;
                Sf[j][2] = (mv1.x == 0) ? -1e9f : Sf[j][2] * 0.125f;
                Sf[j][3] = (mv1.y == 0) ? -1e9f : Sf[j][3] * 0.125f;
            }

            // ---- online softmax ----
            float corr[2];
#pragma unroll
            for (int rr = 0; rr < 2; rr++) {
                float mx = -1e30f;
#pragma unroll
                for (int j = 0; j < 8; j++)
                    mx = fmaxf(mx, fmaxf(Sf[j][rr * 2], Sf[j][rr * 2 + 1]));
                mx = fmaxf(mx, __shfl_xor_sync(0xFFFFFFFF, mx, 1));
                mx = fmaxf(mx, __shfl_xor_sync(0xFFFFFFFF, mx, 2));
                float mnew = fmaxf(mstate[rr], mx);
                corr[rr] = __expf(mstate[rr] - mnew);
                float sum = 0.0f;
#pragma unroll
                for (int j = 0; j < 8; j++) {
                    float p0 = __expf(Sf[j][rr * 2]     - mnew);
                    float p1 = __expf(Sf[j][rr * 2 + 1] - mnew);
                    Sf[j][rr * 2] = p0; Sf[j][rr * 2 + 1] = p1;
                    sum += p0 + p1;
                }
                sum += __shfl_xor_sync(0xFFFFFFFF, sum, 1);
                sum += __shfl_xor_sync(0xFFFFFFFF, sum, 2);
                lstate[rr] = lstate[rr] * corr[rr] + sum;
                mstate[rr] = mnew;
            }

#pragma unroll
            for (int j = 0; j < 8; j++) {
                O[j][0] *= corr[0]; O[j][1] *= corr[0];
                O[j][2] *= corr[1]; O[j][3] *= corr[1];
            }

            // ---- pack P (hi/lo split) ----
            uint32_t aPh[4][4], aPl[4][4];
#pragma unroll
            for (int kc = 0; kc < 4; kc++) {
#pragma unroll
                for (int half = 0; half < 2; half++) {
                    const int j = kc * 2 + half;
#pragma unroll
                    for (int rr = 0; rr < 2; rr++) {
                        float p0 = Sf[j][rr * 2], p1 = Sf[j][rr * 2 + 1];
                        __nv_bfloat16 h0 = __float2bfloat16_rn(p0);
                        __nv_bfloat16 h1 = __float2bfloat16_rn(p1);
                        __nv_bfloat162 hp; hp.x = h0; hp.y = h1;
                        aPh[kc][half * 2 + rr] = *(uint32_t*)&hp;
                        aPl[kc][half * 2 + rr] =
                            packbf(p0 - __bfloat162float(h0), p1 - __bfloat162float(h1));
                    }
                }
            }

            // ---- O += P V (split compensated) ----
#pragma unroll
            for (int kc = 0; kc < 4; kc++) {
#pragma unroll
                for (int jp = 0; jp < 4; jp++) {
                    uint32_t vh[4], vl[4];
                    ldsm4t(vh, voffV + AOFF_VH + (uint32_t)(kc * 16 * ALD) + (uint32_t)(jp * 32));
                    ldsm4t(vl, voffV + AOFF_VL + (uint32_t)(kc * 16 * ALD) + (uint32_t)(jp * 32));
                    mma16816(O[jp * 2],     aPh[kc][0], aPh[kc][1], aPh[kc][2], aPh[kc][3], vh[0], vh[1]);
                    mma16816(O[jp * 2],     aPh[kc][0], aPh[kc][1], aPh[kc][2], aPh[kc][3], vl[0], vl[1]);
                    mma16816(O[jp * 2],     aPl[kc][0], aPl[kc][1], aPl[kc][2], aPl[kc][3], vh[0], vh[1]);
                    mma16816(O[jp * 2 + 1], aPh[kc][0], aPh[kc][1], aPh[kc][2], aPh[kc][3], vh[2], vh[3]);
                    mma16816(O[jp * 2 + 1], aPh[kc][0], aPh[kc][1], aPh[kc][2], aPh[kc][3], vl[2], vl[3]);
                    mma16816(O[jp * 2 + 1], aPl[kc][0], aPl[kc][1], aPl[kc][2], aPl[kc][3], vh[2], vh[3]);
                }
            }
        }

        // ---- finalize: write pre-split context ----
        const float inv0 = 1.0f / lstate[0];
        const float inv1 = 1.0f / lstate[1];
        __nv_bfloat16* Chb = Ch + base;
        __nv_bfloat16* Clb = Cl + base;
#pragma unroll
        for (int j = 0; j < 8; j++) {
            const int col = j * 8 + mcol;
            float v0 = O[j][0] * inv0, v1 = O[j][1] * inv0;
            float v2 = O[j][2] * inv1, v3 = O[j][3] * inv1;
            __nv_bfloat16 h0 = __float2bfloat16_rn(v0);
            __nv_bfloat16 h1 = __float2bfloat16_rn(v1);
            __nv_bfloat16 h2 = __float2bfloat16_rn(v2);
            __nv_bfloat16 h3 = __float2bfloat16_rn(v3);
            __nv_bfloat162 hp0; hp0.x = h0; hp0.y = h1;
            __nv_bfloat162 hp1; hp1.x = h2; hp1.y = h3;
            *(uint32_t*)&Chb[(size_t)row0 * D_ + col]       = *(uint32_t*)&hp0;
            *(uint32_t*)&Chb[(size_t)(row0 + 8) * D_ + col] = *(uint32_t*)&hp1;
            *(uint32_t*)&Clb[(size_t)row0 * D_ + col] =
                packbf(v0 - __bfloat162float(h0), v1 - __bfloat162float(h1));
            *(uint32_t*)&Clb[(size_t)(row0 + 8) * D_ + col] =
                packbf(v2 - __bfloat162float(h2), v3 - __bfloat162float(h3));
        }
    }
}

// ---------------------------------------------------------------------------
// Launch
// ---------------------------------------------------------------------------
extern "C" void kernel_launch(void* const* d_in, const int* in_sizes, int n_in,
                              void* d_out, int out_size)
{
    (void)in_sizes; (void)n_in; (void)out_size;
    const float* q    = (const float*)d_in[0];
    const float* k    = (const float*)d_in[1];
    const float* v    = (const float*)d_in[2];
    const int*   mask = (const int*)d_in[3];
    const float* w_q  = (const float*)d_in[4];
    const float* b_q  = (const float*)d_in[5];
    const float* w_k  = (const float*)d_in[6];
    const float* b_k  = (const float*)d_in[7];
    const float* w_v  = (const float*)d_in[8];
    const float* b_v  = (const float*)d_in[9];
    const float* w_o  = (const float*)d_in[10];
    const float* b_o  = (const float*)d_in[11];
    float* out = (float*)d_out;

    __nv_bfloat16 *gQh, *gQl, *gKh, *gKl, *gVh, *gVl, *gCh, *gCl;
    cudaGetSymbolAddress((void**)&gQh, g_Qh);
    cudaGetSymbolAddress((void**)&gQl, g_Ql);
    cudaGetSymbolAddress((void**)&gKh, g_Kh);
    cudaGetSymbolAddress((void**)&gKl, g_Kl);
    cudaGetSymbolAddress((void**)&gVh, g_Vh);
    cudaGetSymbolAddress((void**)&gVl, g_Vl);
    cudaGetSymbolAddress((void**)&gCh, g_Ch);
    cudaGetSymbolAddress((void**)&gCl, g_Cl);

    cudaFuncSetAttribute(attn_mma_kernel,
                         cudaFuncAttributeMaxDynamicSharedMemorySize,
                         ATTN_SMEM_BYTES);

    dim3 gblk(256);

    // QKV projections: 768 tiles on persistent grid of 296
    gemm_mma_kernel<0><<<NPERS, gblk>>>(
        q, k, v, nullptr, nullptr,
        w_q, w_k, w_v, b_q, b_k, b_v,
        nullptr,
        gQh, gKh, gVh, gQl, gKl, gVl,
        768);

    // attention: 512 tiles on persistent grid of 296
    attn_mma_kernel<<<NPERS, gblk, ATTN_SMEM_BYTES>>>(
        gQh, gQl, gKh, gKl, gVh, gVl, mask, gCh, gCl);

    // final projection: 256 tiles (< 296, one tile per CTA)
    gemm_mma_kernel<1><<<256, gblk>>>(
        nullptr, nullptr, nullptr, gCh, gCl,
        w_o, nullptr, nullptr, b_o, nullptr, nullptr,
        out,
        nullptr, nullptr, nullptr, nullptr, nullptr, nullptr,
        256);
}

// round 15
// speedup vs baseline: 1.0945x; 1.0670x over previous
#include <cuda_runtime.h>
#include <cuda_fp16.h>
#include <cstdint>

// Problem constants
#define B_  2
#define S_  2048
#define D_  1024
#define H_  16
#define DK_ 64
#define M_  (B_ * S_)   // 4096

// ---------------------------------------------------------------------------
// Scratch: Q/K/V and context stored pre-split as fp16 hi/lo.
// ---------------------------------------------------------------------------
__device__ __half g_Qh[M_ * D_];
__device__ __half g_Ql[M_ * D_];   // written by projection, unused by attn (2-term QK)
__device__ __half g_Kh[M_ * D_];
__device__ __half g_Kl[M_ * D_];
__device__ __half g_Vh[M_ * D_];
__device__ __half g_Vl[M_ * D_];
__device__ __half g_Ch[M_ * D_];
__device__ __half g_Cl[M_ * D_];

__device__ __forceinline__ uint32_t smem_u32(const void* p) {
    uint32_t a;
    asm("{ .reg .u64 t; cvta.to.shared.u64 t, %1; cvt.u32.u64 %0, t; }"
        : "=r"(a) : "l"(p));
    return a;
}

// fp16 MMA m16n8k16 (sm_80+ PTX -> valid on compute_103)
__device__ __forceinline__ void mma16816(float* c,
                                         uint32_t a0, uint32_t a1, uint32_t a2, uint32_t a3,
                                         uint32_t b0, uint32_t b1) {
    asm volatile(
        "mma.sync.aligned.m16n8k16.row.col.f32.f16.f16.f32 "
        "{%0,%1,%2,%3}, {%4,%5,%6,%7}, {%8,%9}, {%0,%1,%2,%3};"
        : "+f"(c[0]), "+f"(c[1]), "+f"(c[2]), "+f"(c[3])
        : "r"(a0), "r"(a1), "r"(a2), "r"(a3), "r"(b0), "r"(b1));
}

__device__ __forceinline__ void ldsm4(uint32_t* r, uint32_t addr) {
    asm volatile("ldmatrix.sync.aligned.m8n8.x4.shared.b16 {%0,%1,%2,%3}, [%4];"
                 : "=r"(r[0]), "=r"(r[1]), "=r"(r[2]), "=r"(r[3]) : "r"(addr));
}

__device__ __forceinline__ void ldsm4t(uint32_t* r, uint32_t addr) {
    asm volatile("ldmatrix.sync.aligned.m8n8.x4.trans.shared.b16 {%0,%1,%2,%3}, [%4];"
                 : "=r"(r[0]), "=r"(r[1]), "=r"(r[2]), "=r"(r[3]) : "r"(addr));
}

union PackH4 { uint64_t u; __half b[4]; };

__device__ __forceinline__ void split4(float4 v, uint64_t& hi, uint64_t& lo) {
    PackH4 h, l;
    h.b[0] = __float2half_rn(v.x);
    h.b[1] = __float2half_rn(v.y);
    h.b[2] = __float2half_rn(v.z);
    h.b[3] = __float2half_rn(v.w);
    l.b[0] = __float2half_rn(v.x - __half2float(h.b[0]));
    l.b[1] = __float2half_rn(v.y - __half2float(h.b[1]));
    l.b[2] = __float2half_rn(v.z - __half2float(h.b[2]));
    l.b[3] = __float2half_rn(v.w - __half2float(h.b[3]));
    hi = h.u; lo = l.u;
}

__device__ __forceinline__ uint32_t packh(float a, float b) {
    __half2 t = __halves2half2(__float2half_rn(a), __float2half_rn(b));
    return *(uint32_t*)&t;
}

// ===========================================================================
// Split-fp16 mma.sync GEMM+bias (R12 structure, 3-term compensation).
// MODE 0: fp32 X in, fp16 hi/lo out (QKV projections; z batched)
// MODE 1: pre-split fp16 A in, fp32 out (final projection)
// ===========================================================================
#define BM 128
#define BN 128
#define BK 32

template<int MODE>
__global__ __launch_bounds__(256, 2) void gemm_mma_kernel(
    const float* __restrict__ X0, const float* __restrict__ X1, const float* __restrict__ X2,
    const __half* __restrict__ Ah, const __half* __restrict__ Al,
    const float* __restrict__ W0, const float* __restrict__ W1, const float* __restrict__ W2,
    const float* __restrict__ bias0, const float* __restrict__ bias1, const float* __restrict__ bias2,
    float* __restrict__ Yf,
    __half* __restrict__ Yh0, __half* __restrict__ Yh1, __half* __restrict__ Yh2,
    __half* __restrict__ Yl0, __half* __restrict__ Yl1, __half* __restrict__ Yl2)
{
    __shared__ __align__(128) __half sAh[BM * 40];
    __shared__ __align__(128) __half sAl[BM * 40];
    __shared__ __align__(128) __half sBh[BN * 40];
    __shared__ __align__(128) __half sBl[BN * 40];

    const int tid  = threadIdx.x;
    const int lane = tid & 31;
    const int wid  = tid >> 5;
    const int wm   = wid >> 2;
    const int wn   = wid & 3;
    const int m0 = blockIdx.y * BM;
    const int n0 = blockIdx.x * BN;
    const int z  = blockIdx.z;

    const float* X = (z == 0) ? X0 : (z == 1) ? X1 : X2;
    const float* W = (z == 0) ? W0 : (z == 1) ? W1 : W2;
    const float* bias = (z == 0) ? bias0 : (z == 1) ? bias1 : bias2;
    __half* Yh = (z == 0) ? Yh0 : (z == 1) ? Yh1 : Yh2;
    __half* Yl = (z == 0) ? Yl0 : (z == 1) ? Yl1 : Yl2;

    const uint32_t bAh = smem_u32(sAh);
    const uint32_t bAl = smem_u32(sAl);
    const uint32_t bBh = smem_u32(sBh);
    const uint32_t bBl = smem_u32(sBl);

    const uint32_t aoff = (uint32_t)((lane & 15) * 80 + (lane >> 4) * 16);
    const uint32_t boff = (uint32_t)(((lane & 7) + ((lane >> 4) & 1) * 8) * 80 +
                                     (((lane >> 3) & 1) ? 16 : 0));

    const int lr = tid >> 3;
    const int lc = tid & 7;

    float C[4][4][4];
#pragma unroll
    for (int i = 0; i < 4; i++)
#pragma unroll
        for (int j = 0; j < 4; j++)
#pragma unroll
            for (int t = 0; t < 4; t++) C[i][j][t] = 0.0f;

    for (int k0 = 0; k0 < D_; k0 += BK) {
        __syncthreads();
        if (MODE == 0) {
#pragma unroll
            for (int it = 0; it < 4; it++) {
                const int r = lr + it * 32;
                uint64_t hi, lo;
                float4 xv = *(const float4*)&X[(size_t)(m0 + r) * D_ + k0 + lc * 4];
                split4(xv, hi, lo);
                *(uint64_t*)((char*)sAh + r * 80 + lc * 8) = hi;
                *(uint64_t*)((char*)sAl + r * 80 + lc * 8) = lo;
            }
        } else {
#pragma unroll
            for (int i = 0; i < 2; i++) {
                const int idx = tid + i * 256;
                const int rr = idx >> 2;
                const int cc = idx & 3;
                const size_t g = (size_t)(m0 + rr) * D_ + k0 + cc * 8;
                *(uint4*)((char*)sAh + rr * 80 + cc * 16) = *(const uint4*)&Ah[g];
                *(uint4*)((char*)sAl + rr * 80 + cc * 16) = *(const uint4*)&Al[g];
            }
        }
#pragma unroll
        for (int it = 0; it < 4; it++) {
            const int r = lr + it * 32;
            uint64_t hi, lo;
            float4 wv = *(const float4*)&W[(size_t)(n0 + r) * D_ + k0 + lc * 4];
            split4(wv, hi, lo);
            *(uint64_t*)((char*)sBh + r * 80 + lc * 8) = hi;
            *(uint64_t*)((char*)sBl + r * 80 + lc * 8) = lo;
        }
        __syncthreads();

#pragma unroll
        for (int ks = 0; ks < 2; ks++) {
            const uint32_t kbyte = (uint32_t)(ks * 32);
            uint32_t bh[2][4], bl[2][4];
#pragma unroll
            for (int p = 0; p < 2; p++) {
                ldsm4(bh[p], bBh + (uint32_t)((wn * 32 + p * 16) * 80) + kbyte + boff);
                ldsm4(bl[p], bBl + (uint32_t)((wn * 32 + p * 16) * 80) + kbyte + boff);
            }
            {
                uint32_t a[4][4];
#pragma unroll
                for (int i = 0; i < 4; i++)
                    ldsm4(a[i], bAh + (uint32_t)((wm * 64 + i * 16) * 80) + kbyte + aoff);
#pragma unroll
                for (int i = 0; i < 4; i++)
#pragma unroll
                    for (int j = 0; j < 4; j++) {
                        mma16816(C[i][j], a[i][0], a[i][1], a[i][2], a[i][3],
                                 bh[j >> 1][(j & 1) * 2], bh[j >> 1][(j & 1) * 2 + 1]);
                        mma16816(C[i][j], a[i][0], a[i][1], a[i][2], a[i][3],
                                 bl[j >> 1][(j & 1) * 2], bl[j >> 1][(j & 1) * 2 + 1]);
                    }
            }
            {
                uint32_t a[4][4];
#pragma unroll
                for (int i = 0; i < 4; i++)
                    ldsm4(a[i], bAl + (uint32_t)((wm * 64 + i * 16) * 80) + kbyte + aoff);
#pragma unroll
                for (int i = 0; i < 4; i++)
#pragma unroll
                    for (int j = 0; j < 4; j++)
                        mma16816(C[i][j], a[i][0], a[i][1], a[i][2], a[i][3],
                                 bh[j >> 1][(j & 1) * 2], bh[j >> 1][(j & 1) * 2 + 1]);
            }
        }
    }

    const int qr = lane >> 2;
    const int qc = (lane & 3) * 2;
#pragma unroll
    for (int i = 0; i < 4; i++) {
        const int row0 = m0 + wm * 64 + i * 16 + qr;
#pragma unroll
        for (int j = 0; j < 4; j++) {
            const int col = n0 + wn * 32 + j * 8 + qc;
            const float b0v = bias[col], b1v = bias[col + 1];
            float v0 = C[i][j][0] + b0v, v1 = C[i][j][1] + b1v;
            float v2 = C[i][j][2] + b0v, v3 = C[i][j][3] + b1v;
            if (MODE == 0) {
                __half h0 = __float2half_rn(v0);
                __half h1 = __float2half_rn(v1);
                __half h2 = __float2half_rn(v2);
                __half h3 = __float2half_rn(v3);
                __half2 hp0 = __halves2half2(h0, h1);
                __half2 hp1 = __halves2half2(h2, h3);
                *(uint32_t*)&Yh[(size_t)row0 * D_ + col]       = *(uint32_t*)&hp0;
                *(uint32_t*)&Yh[(size_t)(row0 + 8) * D_ + col] = *(uint32_t*)&hp1;
                *(uint32_t*)&Yl[(size_t)row0 * D_ + col] =
                    packh(v0 - __half2float(h0), v1 - __half2float(h1));
                *(uint32_t*)&Yl[(size_t)(row0 + 8) * D_ + col] =
                    packh(v2 - __half2float(h2), v3 - __half2float(h3));
            } else {
                float2 o0 = { v0, v1 };
                float2 o1 = { v2, v3 };
                *(float2*)&Yf[(size_t)row0 * D_ + col]       = o0;
                *(float2*)&Yf[(size_t)(row0 + 8) * D_ + col] = o1;
            }
        }
    }
}

// ===========================================================================
// Flash attention — R12 body, fp16, 2-term QK (Qh only) and 2-term PV (Ph only).
// smem: QH + KH/KL/VH/VL (QL not needed).
// ===========================================================================
#define ATQ 128
#define ATK 64
#define ALD 144

#define AOFF_QH 0
#define AOFF_KH (ATQ * ALD)                    // 18432
#define AOFF_KL (AOFF_KH + ATK * ALD)
#define AOFF_VH (AOFF_KL + ATK * ALD)
#define AOFF_VL (AOFF_VH + ATK * ALD)
#define ATTN_SMEM_BYTES (AOFF_VL + ATK * ALD)  // 55296

__global__ __launch_bounds__(256) void attn_mma_kernel(
    const __half* __restrict__ Qh,
    const __half* __restrict__ Kh, const __half* __restrict__ Kl,
    const __half* __restrict__ Vh, const __half* __restrict__ Vl,
    const int* __restrict__ mask,
    __half* __restrict__ Ch, __half* __restrict__ Cl)
{
    extern __shared__ __align__(128) char smem[];
    const uint32_t sb = smem_u32(smem);

    const int tid  = threadIdx.x;
    const int lane = tid & 31;
    const int wid  = tid >> 5;
    const int bh = blockIdx.y;
    const int b  = bh >> 4;
    const int h  = bh & 15;
    const int q0 = blockIdx.x * ATQ;

    const size_t base = (size_t)b * S_ * D_ + (size_t)h * DK_;
    const __half* Qhb = Qh + base;
    const __half* Khb = Kh + base;
    const __half* Klb = Kl + base;
    const __half* Vhb = Vh + base;
    const __half* Vlb = Vl + base;
    const int* Mb = mask + (size_t)b * S_ * S_;

    // ---- load Q hi tile (128 x 64): 1024 uint4, 4 per thread ----
#pragma unroll
    for (int i = 0; i < 4; i++) {
        const int idx = tid + i * 256;
        const int rr = idx >> 3;
        const int cc = idx & 7;
        *(uint4*)(smem + AOFF_QH + rr * ALD + cc * 16) =
            *(const uint4*)&Qhb[(size_t)(q0 + rr) * D_ + cc * 8];
    }

    const uint32_t aoffQ = sb + (uint32_t)((wid * 16 + (lane & 15)) * ALD + (lane >> 4) * 16);
    const uint32_t boffK = sb + (uint32_t)(((lane & 7) + ((lane >> 4) & 1) * 8) * ALD +
                                           ((lane >> 3) & 1) * 16);
    const uint32_t voffV = sb + (uint32_t)((((lane >> 3) & 1) * 8 + (lane & 7)) * ALD +
                                           ((lane >> 4) & 1) * 16);

    float mstate[2] = { -1e30f, -1e30f };
    float lstate[2] = { 0.0f, 0.0f };
    float O[8][4];
#pragma unroll
    for (int j = 0; j < 8; j++)
#pragma unroll
        for (int t = 0; t < 4; t++) O[j][t] = 0.0f;

    const int row0 = q0 + wid * 16 + (lane >> 2);
    const int mcol = (lane & 3) * 2;
    const int* mrow0 = Mb + (size_t)row0 * S_;
    const int* mrow1 = Mb + (size_t)(row0 + 8) * S_;

    for (int k0 = 0; k0 < S_; k0 += ATK) {
        __syncthreads();
        // ---- load K,V tiles (hi/lo) ----
#pragma unroll
        for (int i = 0; i < 2; i++) {
            const int idx = tid + i * 256;
            const int rr = idx >> 3;
            const int cc = idx & 7;
            const size_t g = (size_t)(k0 + rr) * D_ + cc * 8;
            *(uint4*)(smem + AOFF_KH + rr * ALD + cc * 16) = *(const uint4*)&Khb[g];
            *(uint4*)(smem + AOFF_KL + rr * ALD + cc * 16) = *(const uint4*)&Klb[g];
            *(uint4*)(smem + AOFF_VH + rr * ALD + cc * 16) = *(const uint4*)&Vhb[g];
            *(uint4*)(smem + AOFF_VL + rr * ALD + cc * 16) = *(const uint4*)&Vlb[g];
        }
        __syncthreads();

        // ---- S = Q K^T (2-term: Qh*Kh + Qh*Kl) ----
        float Sf[8][4];
#pragma unroll
        for (int j = 0; j < 8; j++)
#pragma unroll
            for (int tt = 0; tt < 4; tt++) Sf[j][tt] = 0.0f;

#pragma unroll
        for (int kc = 0; kc < 4; kc++) {
            const uint32_t kb = (uint32_t)(kc * 32);
            uint32_t ah[4];
            ldsm4(ah, aoffQ + AOFF_QH + kb);
#pragma unroll
            for (int jp = 0; jp < 4; jp++) {
                uint32_t kh[4], kl[4];
                ldsm4(kh, boffK + AOFF_KH + (uint32_t)(jp * 16 * ALD) + kb);
                ldsm4(kl, boffK + AOFF_KL + (uint32_t)(jp * 16 * ALD) + kb);
                mma16816(Sf[jp * 2],     ah[0], ah[1], ah[2], ah[3], kh[0], kh[1]);
                mma16816(Sf[jp * 2],     ah[0], ah[1], ah[2], ah[3], kl[0], kl[1]);
                mma16816(Sf[jp * 2 + 1], ah[0], ah[1], ah[2], ah[3], kh[2], kh[3]);
                mma16816(Sf[jp * 2 + 1], ah[0], ah[1], ah[2], ah[3], kl[2], kl[3]);
            }
        }

        // ---- scale + mask ----
#pragma unroll
        for (int j = 0; j < 8; j++) {
            int2 mv0 = *(const int2*)&mrow0[k0 + j * 8 + mcol];
            int2 mv1 = *(const int2*)&mrow1[k0 + j * 8 + mcol];
            Sf[j][0] = (mv0.x == 0) ? -1e9f : Sf[j][0] * 0.125f;
            Sf[j][1] = (mv0.y == 0) ? -1e9f : Sf[j][1] * 0.125f;
            Sf[j][2] = (mv1.x == 0) ? -1e9f : Sf[j][2] * 0.125f;
            Sf[j][3] = (mv1.y == 0) ? -1e9f : Sf[j][3] * 0.125f;
        }

        // ---- online softmax ----
        float corr[2];
#pragma unroll
        for (int rr = 0; rr < 2; rr++) {
            float mx = -1e30f;
#pragma unroll
            for (int j = 0; j < 8; j++)
                mx = fmaxf(mx, fmaxf(Sf[j][rr * 2], Sf[j][rr * 2 + 1]));
            mx = fmaxf(mx, __shfl_xor_sync(0xFFFFFFFF, mx, 1));
            mx = fmaxf(mx, __shfl_xor_sync(0xFFFFFFFF, mx, 2));
            float mnew = fmaxf(mstate[rr], mx);
            corr[rr] = __expf(mstate[rr] - mnew);
            float sum = 0.0f;
#pragma unroll
            for (int j = 0; j < 8; j++) {
                float p0 = __expf(Sf[j][rr * 2]     - mnew);
                float p1 = __expf(Sf[j][rr * 2 + 1] - mnew);
                Sf[j][rr * 2] = p0; Sf[j][rr * 2 + 1] = p1;
                sum += p0 + p1;
            }
            sum += __shfl_xor_sync(0xFFFFFFFF, sum, 1);
            sum += __shfl_xor_sync(0xFFFFFFFF, sum, 2);
            lstate[rr] = lstate[rr] * corr[rr] + sum;
            mstate[rr] = mnew;
        }

#pragma unroll
        for (int j = 0; j < 8; j++) {
            O[j][0] *= corr[0]; O[j][1] *= corr[0];
            O[j][2] *= corr[1]; O[j][3] *= corr[1];
        }

        // ---- pack P hi only (2-term PV) ----
        uint32_t aPh[4][4];
#pragma unroll
        for (int kc = 0; kc < 4; kc++) {
#pragma unroll
            for (int half = 0; half < 2; half++) {
                const int j = kc * 2 + half;
#pragma unroll
                for (int rr = 0; rr < 2; rr++) {
                    __half2 hp = __halves2half2(__float2half_rn(Sf[j][rr * 2]),
                                                __float2half_rn(Sf[j][rr * 2 + 1]));
                    aPh[kc][half * 2 + rr] = *(uint32_t*)&hp;
                }
            }
        }

        // ---- O += P V (2-term: Ph*Vh + Ph*Vl) ----
#pragma unroll
        for (int kc = 0; kc < 4; kc++) {
#pragma unroll
            for (int jp = 0; jp < 4; jp++) {
                uint32_t vh[4], vl[4];
                ldsm4t(vh, voffV + AOFF_VH + (uint32_t)(kc * 16 * ALD) + (uint32_t)(jp * 32));
                ldsm4t(vl, voffV + AOFF_VL + (uint32_t)(kc * 16 * ALD) + (uint32_t)(jp * 32));
                mma16816(O[jp * 2],     aPh[kc][0], aPh[kc][1], aPh[kc][2], aPh[kc][3], vh[0], vh[1]);
                mma16816(O[jp * 2],     aPh[kc][0], aPh[kc][1], aPh[kc][2], aPh[kc][3], vl[0], vl[1]);
                mma16816(O[jp * 2 + 1], aPh[kc][0], aPh[kc][1], aPh[kc][2], aPh[kc][3], vh[2], vh[3]);
                mma16816(O[jp * 2 + 1], aPh[kc][0], aPh[kc][1], aPh[kc][2], aPh[kc][3], vl[2], vl[3]);
            }
        }
        __syncthreads();
    }

    // ---- finalize: write pre-split context (hi/lo, for 3-term final GEMM) ----
    const float inv0 = 1.0f / lstate[0];
    const float inv1 = 1.0f / lstate[1];
    __half* Chb = Ch + base;
    __half* Clb = Cl + base;
#pragma unroll
    for (int j = 0; j < 8; j++) {
        const int col = j * 8 + mcol;
        float v0 = O[j][0] * inv0, v1 = O[j][1] * inv0;
        float v2 = O[j][2] * inv1, v3 = O[j][3] * inv1;
        __half h0 = __float2half_rn(v0);
        __half h1 = __float2half_rn(v1);
        __half h2 = __float2half_rn(v2);
        __half h3 = __float2half_rn(v3);
        __half2 hp0 = __halves2half2(h0, h1);
        __half2 hp1 = __halves2half2(h2, h3);
        *(uint32_t*)&Chb[(size_t)row0 * D_ + col]       = *(uint32_t*)&hp0;
        *(uint32_t*)&Chb[(size_t)(row0 + 8) * D_ + col] = *(uint32_t*)&hp1;
        *(uint32_t*)&Clb[(size_t)row0 * D_ + col] =
            packh(v0 - __half2float(h0), v1 - __half2float(h1));
        *(uint32_t*)&Clb[(size_t)(row0 + 8) * D_ + col] =
            packh(v2 - __half2float(h2), v3 - __half2float(h3));
    }
}

// ---------------------------------------------------------------------------
// Launch
// ---------------------------------------------------------------------------
extern "C" void kernel_launch(void* const* d_in, const int* in_sizes, int n_in,
                              void* d_out, int out_size)
{
    (void)in_sizes; (void)n_in; (void)out_size;
    const float* q    = (const float*)d_in[0];
    const float* k    = (const float*)d_in[1];
    const float* v    = (const float*)d_in[2];
    const int*   mask = (const int*)d_in[3];
    const float* w_q  = (const float*)d_in[4];
    const float* b_q  = (const float*)d_in[5];
    const float* w_k  = (const float*)d_in[6];
    const float* b_k  = (const float*)d_in[7];
    const float* w_v  = (const float*)d_in[8];
    const float* b_v  = (const float*)d_in[9];
    const float* w_o  = (const float*)d_in[10];
    const float* b_o  = (const float*)d_in[11];
    float* out = (float*)d_out;

    __half *gQh, *gQl, *gKh, *gKl, *gVh, *gVl, *gCh, *gCl;
    cudaGetSymbolAddress((void**)&gQh, g_Qh);
    cudaGetSymbolAddress((void**)&gQl, g_Ql);
    cudaGetSymbolAddress((void**)&gKh, g_Kh);
    cudaGetSymbolAddress((void**)&gKl, g_Kl);
    cudaGetSymbolAddress((void**)&gVh, g_Vh);
    cudaGetSymbolAddress((void**)&gVl, g_Vl);
    cudaGetSymbolAddress((void**)&gCh, g_Ch);
    cudaGetSymbolAddress((void**)&gCl, g_Cl);

    cudaFuncSetAttribute(attn_mma_kernel,
                         cudaFuncAttributeMaxDynamicSharedMemorySize,
                         ATTN_SMEM_BYTES);

    dim3 gblk(256);

    // Q/K/V projections batched over z (fp16 3-term)
    dim3 ggrid3(D_ / BN, M_ / BM, 3);
    gemm_mma_kernel<0><<<ggrid3, gblk>>>(
        q, k, v, nullptr, nullptr,
        w_q, w_k, w_v, b_q, b_k, b_v,
        nullptr,
        gQh, gKh, gVh, gQl, gKl, gVl);

    dim3 ablk(256);
    dim3 agrid(S_ / ATQ, B_ * H_);    // (16, 32)
    attn_mma_kernel<<<agrid, ablk, ATTN_SMEM_BYTES>>>(
        gQh, gKh, gKl, gVh, gVl, mask, gCh, gCl);

    // final projection (pre-split A, fp16 3-term)
    dim3 ggrid1(D_ / BN, M_ / BM, 1);
    gemm_mma_kernel<1><<<ggrid1, gblk>>>(
        nullptr, nullptr, nullptr, gCh, gCl,
        w_o, nullptr, nullptr, b_o, nullptr, nullptr,
        out,
        nullptr, nullptr, nullptr, nullptr, nullptr, nullptr);
}